// round 1
// baseline (speedup 1.0000x reference)
#include <cuda_runtime.h>
#include <math.h>

#define Bn 16
#define C  128
#define Hh 64
#define Ww 64
#define P  4096      // Hh*Ww
#define TD 256
#define CD 256
#define E  8
#define NK 2
#define PT 32        // pixel tile for pointwise GEMMs

// ---------------- scratch (static device arrays: allocation-guard safe) ----
__device__ float g_t1[Bn*C*P];          // dwconv(proj) output
__device__ float g_xproj[Bn*C*P];       // x_proj
__device__ float g_t2[Bn*NK*C*P];       // expert dwconv outputs (routed)
__device__ float g_pooled[Bn*C];
__device__ int   g_eidx[Bn*NK];
__device__ float g_ew[Bn*NK];

__device__ __forceinline__ float silu_f(float v) {
    return v / (1.f + __expf(-v));
}

// ---------------- 1) proj depthwise 3x3 -----------------------------------
__global__ void dw_proj_kernel(const float* __restrict__ x,
                               const float* __restrict__ w,
                               const float* __restrict__ bias) {
    int idx = blockIdx.x * blockDim.x + threadIdx.x;
    if (idx >= Bn*C*P) return;
    int px = idx & 63;
    int py = (idx >> 6) & 63;
    int plane = idx >> 12;           // b*C + c
    int c = plane & 127;
    const float* xp = x + ((size_t)plane << 12);
    const float* wc = w + c * 9;
    float acc = bias[c];
    #pragma unroll
    for (int dy = -1; dy <= 1; dy++) {
        int yy = py + dy;
        if ((unsigned)yy >= 64u) continue;
        #pragma unroll
        for (int dx = -1; dx <= 1; dx++) {
            int xx = px + dx;
            if ((unsigned)xx >= 64u) continue;
            acc += wc[(dy+1)*3 + (dx+1)] * xp[(yy << 6) + xx];
        }
    }
    g_t1[idx] = acc;
}

// ---------------- 2) proj pointwise 1x1 (GEMM) -----------------------------
__global__ __launch_bounds__(128)
void pw_proj_kernel(const float* __restrict__ Wm, const float* __restrict__ bias) {
    int b  = blockIdx.y;
    int p0 = blockIdx.x * PT;
    int co = threadIdx.x;            // 128 threads = 128 output channels
    __shared__ float Wt[C][17];      // padded: no bank conflicts on Wt[co][ci]
    __shared__ float tt[16][PT];
    float acc[PT];
    #pragma unroll
    for (int p = 0; p < PT; p++) acc[p] = 0.f;
    const float* tin = g_t1 + (((size_t)b * C) << 12) + p0;
    for (int ci0 = 0; ci0 < C; ci0 += 16) {
        __syncthreads();
        #pragma unroll
        for (int i = 0; i < 16; i++) {
            int lin = i * 128 + co;
            Wt[lin >> 4][lin & 15] = Wm[(lin >> 4) * C + ci0 + (lin & 15)];
        }
        #pragma unroll
        for (int i = 0; i < 4; i++) {
            int lin = i * 128 + co;
            tt[lin >> 5][lin & 31] = tin[(size_t)(ci0 + (lin >> 5)) * P + (lin & 31)];
        }
        __syncthreads();
        #pragma unroll
        for (int ci = 0; ci < 16; ci++) {
            float wv = Wt[co][ci];
            #pragma unroll
            for (int p = 0; p < PT; p++) acc[p] += wv * tt[ci][p];
        }
    }
    float bb = bias[co];
    float* op = g_xproj + ((((size_t)b * C) + co) << 12) + p0;
    #pragma unroll
    for (int p = 0; p < PT; p++) op[p] = acc[p] + bb;
}

// ---------------- 3) global average pool -----------------------------------
__global__ void pool_kernel() {
    int plane = blockIdx.x;          // b*C + c
    const float* p = g_xproj + ((size_t)plane << 12);
    float s = 0.f;
    for (int i = threadIdx.x; i < P; i += 256) s += p[i];
    __shared__ float sm[8];
    #pragma unroll
    for (int o = 16; o; o >>= 1) s += __shfl_down_sync(0xffffffffu, s, o);
    if ((threadIdx.x & 31) == 0) sm[threadIdx.x >> 5] = s;
    __syncthreads();
    if (threadIdx.x == 0) {
        float t = 0.f;
        #pragma unroll
        for (int i = 0; i < 8; i++) t += sm[i];
        g_pooled[plane] = t * (1.f / 4096.f);
    }
}

// ---------------- 4) router MLP + top-2 + softmax --------------------------
__global__ void router_kernel(const float* __restrict__ t_emb,
                              const float* __restrict__ c_emb,
                              const float* __restrict__ W1, const float* __restrict__ b1,
                              const float* __restrict__ W2, const float* __restrict__ b2,
                              float* __restrict__ out_logits) {
    __shared__ float h_sm[Bn][C];
    __shared__ float lg[Bn][E];
    int t = threadIdx.x;
    for (int id = t; id < Bn * C; id += 1024) {
        int b = id >> 7, co = id & 127;
        float acc = b1[co];
        const float* pb = g_pooled + b * C;
        for (int f = 0; f < C;  f++) acc += pb[f] * W1[f * C + co];
        const float* tb = t_emb + b * TD;
        for (int f = 0; f < TD; f++) acc += tb[f] * W1[(C + f) * C + co];
        const float* cb = c_emb + b * CD;
        for (int f = 0; f < CD; f++) acc += cb[f] * W1[(C + TD + f) * C + co];
        h_sm[b][co] = silu_f(acc);
    }
    __syncthreads();
    if (t < Bn * E) {
        int b = t >> 3, e = t & 7;
        float acc = b2[e];
        for (int ci = 0; ci < C; ci++) acc += h_sm[b][ci] * W2[ci * E + e];
        lg[b][e] = acc;
        out_logits[b * E + e] = acc;
    }
    __syncthreads();
    if (t < Bn) {
        int b = t;
        int i0 = 0; float v0 = lg[b][0];
        for (int e = 1; e < E; e++) if (lg[b][e] > v0) { v0 = lg[b][e]; i0 = e; }
        int i1 = -1; float v1 = -3.0e38f;
        for (int e = 0; e < E; e++) {
            if (e == i0) continue;
            if (lg[b][e] > v1) { v1 = lg[b][e]; i1 = e; }
        }
        float w0 = 1.f / (1.f + __expf(v1 - v0));   // softmax over (v0,v1), v0>=v1
        g_eidx[b*2]   = i0;  g_eidx[b*2+1] = i1;
        g_ew[b*2]     = w0;  g_ew[b*2+1]   = 1.f - w0;
    }
}

// ---------------- 5) routed expert depthwise 3x3 ---------------------------
__global__ void dw_exp_kernel(const float* __restrict__ w,
                              const float* __restrict__ bias) {
    int idx = blockIdx.x * blockDim.x + threadIdx.x;
    if (idx >= Bn*NK*C*P) return;
    int px = idx & 63;
    int py = (idx >> 6) & 63;
    int c  = (idx >> 12) & 127;
    int k  = (idx >> 19) & 1;
    int b  = idx >> 20;
    int e  = g_eidx[b * NK + k];
    const float* xp = g_xproj + ((((size_t)b * C) + c) << 12);
    const float* wc = w + ((size_t)e * C + c) * 9;
    float acc = bias[e * C + c];
    #pragma unroll
    for (int dy = -1; dy <= 1; dy++) {
        int yy = py + dy;
        if ((unsigned)yy >= 64u) continue;
        #pragma unroll
        for (int dx = -1; dx <= 1; dx++) {
            int xx = px + dx;
            if ((unsigned)xx >= 64u) continue;
            acc += wc[(dy+1)*3 + (dx+1)] * xp[(yy << 6) + xx];
        }
    }
    g_t2[idx] = acc;
}

// ---------------- 6) expert pointwise GEMM ×2 + silu + weighted mix --------
__global__ __launch_bounds__(128)
void pw_exp_kernel(const float* __restrict__ Wm, const float* __restrict__ bias,
                   float* __restrict__ out) {
    int b  = blockIdx.y;
    int p0 = blockIdx.x * PT;
    int co = threadIdx.x;
    int e0 = g_eidx[b*2], e1 = g_eidx[b*2+1];
    float rw0 = g_ew[b*2], rw1 = g_ew[b*2+1];
    __shared__ float Wt0[C][17], Wt1[C][17];
    __shared__ float tt0[16][PT], tt1[16][PT];
    float acc0[PT], acc1[PT];
    #pragma unroll
    for (int p = 0; p < PT; p++) { acc0[p] = 0.f; acc1[p] = 0.f; }
    const float* t0 = g_t2 + (((size_t)(b*2 + 0) * C) << 12) + p0;
    const float* t1 = g_t2 + (((size_t)(b*2 + 1) * C) << 12) + p0;
    const float* W0 = Wm + (size_t)e0 * C * C;
    const float* W1 = Wm + (size_t)e1 * C * C;
    for (int ci0 = 0; ci0 < C; ci0 += 16) {
        __syncthreads();
        #pragma unroll
        for (int i = 0; i < 16; i++) {
            int lin = i * 128 + co;
            int r = lin >> 4, cc = lin & 15;
            Wt0[r][cc] = W0[r * C + ci0 + cc];
            Wt1[r][cc] = W1[r * C + ci0 + cc];
        }
        #pragma unroll
        for (int i = 0; i < 4; i++) {
            int lin = i * 128 + co;
            int r = lin >> 5, pp = lin & 31;
            tt0[r][pp] = t0[(size_t)(ci0 + r) * P + pp];
            tt1[r][pp] = t1[(size_t)(ci0 + r) * P + pp];
        }
        __syncthreads();
        #pragma unroll
        for (int ci = 0; ci < 16; ci++) {
            float w0 = Wt0[co][ci];
            float w1 = Wt1[co][ci];
            #pragma unroll
            for (int p = 0; p < PT; p++) {
                acc0[p] += w0 * tt0[ci][p];
                acc1[p] += w1 * tt1[ci][p];
            }
        }
    }
    float bb0 = bias[e0 * C + co];
    float bb1 = bias[e1 * C + co];
    float* op = out + ((((size_t)b * C) + co) << 12) + p0;
    #pragma unroll
    for (int p = 0; p < PT; p++) {
        op[p] = rw0 * silu_f(acc0[p] + bb0) + rw1 * silu_f(acc1[p] + bb1);
    }
}

// ---------------- launch ----------------------------------------------------
extern "C" void kernel_launch(void* const* d_in, const int* in_sizes, int n_in,
                              void* d_out, int out_size) {
    const float* x         = (const float*)d_in[0];
    const float* t_emb     = (const float*)d_in[1];
    const float* c_emb     = (const float*)d_in[2];
    const float* proj_dw   = (const float*)d_in[3];
    const float* proj_dw_b = (const float*)d_in[4];
    const float* proj_pw   = (const float*)d_in[5];
    const float* proj_pw_b = (const float*)d_in[6];
    const float* r_w1      = (const float*)d_in[7];
    const float* r_b1      = (const float*)d_in[8];
    const float* r_w2      = (const float*)d_in[9];
    const float* r_b2      = (const float*)d_in[10];
    const float* exp_dw    = (const float*)d_in[11];
    const float* exp_dw_b  = (const float*)d_in[12];
    const float* exp_pw    = (const float*)d_in[13];
    const float* exp_pw_b  = (const float*)d_in[14];

    float* out        = (float*)d_out;
    float* out_logits = out + (size_t)Bn * C * P;   // [16,8] appended after main output

    dw_proj_kernel<<<(Bn*C*P + 255) / 256, 256>>>(x, proj_dw, proj_dw_b);
    pw_proj_kernel<<<dim3(P / PT, Bn), C>>>(proj_pw, proj_pw_b);
    pool_kernel<<<Bn * C, 256>>>();
    router_kernel<<<1, 1024>>>(t_emb, c_emb, r_w1, r_b1, r_w2, r_b2, out_logits);
    dw_exp_kernel<<<(Bn*NK*C*P + 255) / 256, 256>>>(exp_dw, exp_dw_b);
    pw_exp_kernel<<<dim3(P / PT, Bn), C>>>(exp_pw, exp_pw_b, out);
}

// round 2
// speedup vs baseline: 1.4842x; 1.4842x over previous
#include <cuda_runtime.h>
#include <math.h>

#define Bn 16
#define C  128
#define P  4096      // 64*64
#define TD 256
#define CD 256
#define E  8
#define NK 2

// ---------------- scratch (static device arrays: allocation-guard safe) ----
__device__ float g_t1[Bn*C*P];          // dwconv(proj) output
__device__ float g_xproj[Bn*C*P];       // x_proj
__device__ float g_t2[Bn*NK*C*P];       // expert dwconv outputs (routed)
__device__ float g_pooled[Bn*C];
__device__ int   g_eidx[Bn*NK];
__device__ float g_ew[Bn*NK];

__device__ __forceinline__ float silu_f(float v) {
    return v / (1.f + __expf(-v));
}

// ---- packed f32x2 helpers (sm_10x FFMA2: 2 FMAs per issue) ----------------
__device__ __forceinline__ unsigned long long pack2(float v) {
    unsigned long long r; unsigned u = __float_as_uint(v);
    asm("mov.b64 %0, {%1, %1};" : "=l"(r) : "r"(u));
    return r;
}
__device__ __forceinline__ void fma2(unsigned long long &d,
                                     unsigned long long a, unsigned long long b) {
    asm("fma.rn.f32x2 %0, %1, %2, %3;" : "=l"(d) : "l"(a), "l"(b), "l"(d));
}
__device__ __forceinline__ float2 unpack2(unsigned long long v) {
    unsigned lo, hi;
    asm("mov.b64 {%0, %1}, %2;" : "=r"(lo), "=r"(hi) : "l"(v));
    return make_float2(__uint_as_float(lo), __uint_as_float(hi));
}

// ---------------- 1) proj depthwise 3x3 (4 px / thread) --------------------
__global__ void dw_proj_kernel(const float* __restrict__ x,
                               const float* __restrict__ w,
                               const float* __restrict__ bias) {
    int idx = blockIdx.x * blockDim.x + threadIdx.x;   // over Bn*C*1024
    if (idx >= Bn*C*1024) return;
    int q = idx & 1023;
    int px0 = (q & 15) << 2;
    int py  = q >> 4;
    int plane = idx >> 10;            // b*C + c
    int c = plane & 127;
    const float* xp = x + ((size_t)plane << 12);
    const float* wc = w + c * 9;
    float bb = bias[c];
    float acc0 = bb, acc1 = bb, acc2 = bb, acc3 = bb;
    #pragma unroll
    for (int dy = -1; dy <= 1; dy++) {
        int yy = py + dy;
        if ((unsigned)yy >= 64u) continue;
        const float* row = xp + (yy << 6);
        float4 m = *(const float4*)&row[px0];
        float rl = (px0 == 0)  ? 0.f : row[px0 - 1];
        float rr = (px0 == 60) ? 0.f : row[px0 + 4];
        float w0 = wc[(dy+1)*3], w1 = wc[(dy+1)*3+1], w2 = wc[(dy+1)*3+2];
        acc0 += w0*rl  + w1*m.x + w2*m.y;
        acc1 += w0*m.x + w1*m.y + w2*m.z;
        acc2 += w0*m.y + w1*m.z + w2*m.w;
        acc3 += w0*m.z + w1*m.w + w2*rr;
    }
    *(float4*)&g_t1[((size_t)plane << 12) + (py << 6) + px0] =
        make_float4(acc0, acc1, acc2, acc3);
}

// ---------------- 2) proj pointwise 1x1 (GEMM, f32x2) ----------------------
// block 256 thr: thread tile = 4 co x 8 px (4 packed pairs). ptile = 64 px.
__global__ __launch_bounds__(256)
void pw_proj_kernel(const float* __restrict__ Wm, const float* __restrict__ bias) {
    int b  = blockIdx.y;
    int p0 = blockIdx.x * 64;
    int tx = threadIdx.x;
    int cg = tx >> 3;                 // 0..31 -> co0 = cg*4
    int pg = tx & 7;                  // 0..7  -> px  = pg*8
    int co0 = cg << 2;
    __shared__ float Wt[C][17];       // Wt[co][k]
    __shared__ float tt[16][64];      // tt[k][px]
    unsigned long long acc[4][4];
    #pragma unroll
    for (int i = 0; i < 4; i++)
        #pragma unroll
        for (int j = 0; j < 4; j++) acc[i][j] = 0ULL;

    const float* tin = g_t1 + (((size_t)b * C) << 12) + p0;
    for (int ci0 = 0; ci0 < C; ci0 += 16) {
        __syncthreads();
        #pragma unroll
        for (int i = 0; i < 8; i++) {     // 2048 W entries / 256 thr
            int lin = i * 256 + tx;
            int co = lin >> 4, k = lin & 15;
            Wt[co][k] = Wm[co * C + ci0 + k];
        }
        #pragma unroll
        for (int i = 0; i < 4; i++) {     // 1024 t entries / 256 thr
            int lin = i * 256 + tx;
            int k = lin >> 6, p = lin & 63;
            tt[k][p] = tin[(size_t)(ci0 + k) * P + p];
        }
        __syncthreads();
        #pragma unroll
        for (int k = 0; k < 16; k++) {
            ulonglong2 u0 = *(const ulonglong2*)&tt[k][pg * 8];
            ulonglong2 u1 = *(const ulonglong2*)&tt[k][pg * 8 + 4];
            unsigned long long tp[4] = {u0.x, u0.y, u1.x, u1.y};
            #pragma unroll
            for (int i = 0; i < 4; i++) {
                unsigned long long w2 = pack2(Wt[co0 + i][k]);
                #pragma unroll
                for (int j = 0; j < 4; j++) fma2(acc[i][j], w2, tp[j]);
            }
        }
    }
    #pragma unroll
    for (int i = 0; i < 4; i++) {
        float bb = bias[co0 + i];
        float* op = g_xproj + ((((size_t)b * C) + co0 + i) << 12) + p0 + pg * 8;
        float r[8];
        #pragma unroll
        for (int j = 0; j < 4; j++) {
            float2 v = unpack2(acc[i][j]);
            r[j*2] = v.x + bb; r[j*2+1] = v.y + bb;
        }
        *(float4*)&op[0] = make_float4(r[0], r[1], r[2], r[3]);
        *(float4*)&op[4] = make_float4(r[4], r[5], r[6], r[7]);
    }
}

// ---------------- 3) global average pool -----------------------------------
__global__ void pool_kernel() {
    int plane = blockIdx.x;           // b*C + c
    const float4* p = (const float4*)(g_xproj + ((size_t)plane << 12));
    float s = 0.f;
    for (int i = threadIdx.x; i < 1024; i += 256) {
        float4 v = p[i];
        s += v.x + v.y + v.z + v.w;
    }
    __shared__ float sm[8];
    #pragma unroll
    for (int o = 16; o; o >>= 1) s += __shfl_down_sync(0xffffffffu, s, o);
    if ((threadIdx.x & 31) == 0) sm[threadIdx.x >> 5] = s;
    __syncthreads();
    if (threadIdx.x == 0) {
        float t = 0.f;
        #pragma unroll
        for (int i = 0; i < 8; i++) t += sm[i];
        g_pooled[plane] = t * (1.f / 4096.f);
    }
}

// ---------------- 4) router: per-b block, fused MLP+top2 -------------------
__global__ __launch_bounds__(512)
void router_kernel(const float* __restrict__ t_emb,
                   const float* __restrict__ c_emb,
                   const float* __restrict__ W1, const float* __restrict__ b1,
                   const float* __restrict__ W2, const float* __restrict__ b2,
                   float* __restrict__ out_logits) {
    int b = blockIdx.x;
    __shared__ float feat[C + TD + CD];
    __shared__ float hpart[4][C];
    __shared__ float h[C];
    __shared__ float lg[E];
    int t = threadIdx.x;
    for (int i = t; i < C + TD + CD; i += 512) {
        float v;
        if (i < C)            v = g_pooled[b * C + i];
        else if (i < C + TD)  v = t_emb[b * TD + (i - C)];
        else                  v = c_emb[b * CD + (i - C - TD)];
        feat[i] = v;
    }
    __syncthreads();
    int co = t & 127, chunk = t >> 7;            // 4 chunks of 160 features
    float acc = 0.f;
    int f0 = chunk * 160;
    #pragma unroll 4
    for (int f = f0; f < f0 + 160; f++) acc += feat[f] * W1[f * C + co];
    hpart[chunk][co] = acc;
    __syncthreads();
    if (t < C) {
        float v = b1[t] + hpart[0][t] + hpart[1][t] + hpart[2][t] + hpart[3][t];
        h[t] = silu_f(v);
    }
    __syncthreads();
    if (t < E) {
        float a = b2[t];
        #pragma unroll 8
        for (int ci = 0; ci < C; ci++) a += h[ci] * W2[ci * E + t];
        lg[t] = a;
        out_logits[b * E + t] = a;
    }
    __syncthreads();
    if (t == 0) {
        int i0 = 0; float v0 = lg[0];
        for (int e = 1; e < E; e++) if (lg[e] > v0) { v0 = lg[e]; i0 = e; }
        int i1 = -1; float v1 = -3.0e38f;
        for (int e = 0; e < E; e++) {
            if (e == i0) continue;
            if (lg[e] > v1) { v1 = lg[e]; i1 = e; }
        }
        float w0 = 1.f / (1.f + __expf(v1 - v0));
        g_eidx[b*2]   = i0;  g_eidx[b*2+1] = i1;
        g_ew[b*2]     = w0;  g_ew[b*2+1]   = 1.f - w0;
    }
}

// ---------------- 5) routed expert depthwise 3x3 (4 px / thread) -----------
__global__ void dw_exp_kernel(const float* __restrict__ w,
                              const float* __restrict__ bias) {
    int idx = blockIdx.x * blockDim.x + threadIdx.x;   // over Bn*NK*C*1024
    if (idx >= Bn*NK*C*1024) return;
    int q = idx & 1023;
    int px0 = (q & 15) << 2;
    int py  = q >> 4;
    int rest = idx >> 10;
    int c = rest & 127;
    int k = (rest >> 7) & 1;
    int b = rest >> 8;
    int e = g_eidx[b * NK + k];
    const float* xp = g_xproj + ((((size_t)b * C) + c) << 12);
    const float* wc = w + ((size_t)e * C + c) * 9;
    float bb = bias[e * C + c];
    float acc0 = bb, acc1 = bb, acc2 = bb, acc3 = bb;
    #pragma unroll
    for (int dy = -1; dy <= 1; dy++) {
        int yy = py + dy;
        if ((unsigned)yy >= 64u) continue;
        const float* row = xp + (yy << 6);
        float4 m = *(const float4*)&row[px0];
        float rl = (px0 == 0)  ? 0.f : row[px0 - 1];
        float rr = (px0 == 60) ? 0.f : row[px0 + 4];
        float w0 = wc[(dy+1)*3], w1 = wc[(dy+1)*3+1], w2 = wc[(dy+1)*3+2];
        acc0 += w0*rl  + w1*m.x + w2*m.y;
        acc1 += w0*m.x + w1*m.y + w2*m.z;
        acc2 += w0*m.y + w1*m.z + w2*m.w;
        acc3 += w0*m.z + w1*m.w + w2*rr;
    }
    *(float4*)&g_t2[((size_t)(((b*2 + k) * C) + c) << 12) + (py << 6) + px0] =
        make_float4(acc0, acc1, acc2, acc3);
}

// ---------------- 6) expert pointwise GEMM x2 + silu + mix (f32x2) ---------
__global__ __launch_bounds__(256)
void pw_exp_kernel(const float* __restrict__ Wm, const float* __restrict__ bias,
                   float* __restrict__ out) {
    int b  = blockIdx.y;
    int p0 = blockIdx.x * 64;
    int tx = threadIdx.x;
    int cg = tx >> 3, pg = tx & 7;
    int co0 = cg << 2;
    int e0 = g_eidx[b*2], e1 = g_eidx[b*2+1];
    float rw0 = g_ew[b*2], rw1 = g_ew[b*2+1];
    __shared__ float Wt0[C][17], Wt1[C][17];
    __shared__ float tt0[16][64], tt1[16][64];
    unsigned long long a0[4][4], a1[4][4];
    #pragma unroll
    for (int i = 0; i < 4; i++)
        #pragma unroll
        for (int j = 0; j < 4; j++) { a0[i][j] = 0ULL; a1[i][j] = 0ULL; }

    const float* t0 = g_t2 + (((size_t)(b*2 + 0) * C) << 12) + p0;
    const float* t1 = g_t2 + (((size_t)(b*2 + 1) * C) << 12) + p0;
    const float* W0 = Wm + (size_t)e0 * C * C;
    const float* W1 = Wm + (size_t)e1 * C * C;
    for (int ci0 = 0; ci0 < C; ci0 += 16) {
        __syncthreads();
        #pragma unroll
        for (int i = 0; i < 8; i++) {
            int lin = i * 256 + tx;
            int co = lin >> 4, k = lin & 15;
            Wt0[co][k] = W0[co * C + ci0 + k];
            Wt1[co][k] = W1[co * C + ci0 + k];
        }
        #pragma unroll
        for (int i = 0; i < 4; i++) {
            int lin = i * 256 + tx;
            int k = lin >> 6, p = lin & 63;
            tt0[k][p] = t0[(size_t)(ci0 + k) * P + p];
            tt1[k][p] = t1[(size_t)(ci0 + k) * P + p];
        }
        __syncthreads();
        #pragma unroll
        for (int k = 0; k < 16; k++) {
            ulonglong2 u0 = *(const ulonglong2*)&tt0[k][pg * 8];
            ulonglong2 u1 = *(const ulonglong2*)&tt0[k][pg * 8 + 4];
            unsigned long long tp0[4] = {u0.x, u0.y, u1.x, u1.y};
            ulonglong2 v0 = *(const ulonglong2*)&tt1[k][pg * 8];
            ulonglong2 v1 = *(const ulonglong2*)&tt1[k][pg * 8 + 4];
            unsigned long long tp1[4] = {v0.x, v0.y, v1.x, v1.y};
            #pragma unroll
            for (int i = 0; i < 4; i++) {
                unsigned long long w20 = pack2(Wt0[co0 + i][k]);
                unsigned long long w21 = pack2(Wt1[co0 + i][k]);
                #pragma unroll
                for (int j = 0; j < 4; j++) {
                    fma2(a0[i][j], w20, tp0[j]);
                    fma2(a1[i][j], w21, tp1[j]);
                }
            }
        }
    }
    #pragma unroll
    for (int i = 0; i < 4; i++) {
        float bb0 = bias[e0 * C + co0 + i];
        float bb1 = bias[e1 * C + co0 + i];
        float* op = out + ((((size_t)b * C) + co0 + i) << 12) + p0 + pg * 8;
        float r[8];
        #pragma unroll
        for (int j = 0; j < 4; j++) {
            float2 x0 = unpack2(a0[i][j]);
            float2 x1 = unpack2(a1[i][j]);
            r[j*2]   = rw0 * silu_f(x0.x + bb0) + rw1 * silu_f(x1.x + bb1);
            r[j*2+1] = rw0 * silu_f(x0.y + bb0) + rw1 * silu_f(x1.y + bb1);
        }
        *(float4*)&op[0] = make_float4(r[0], r[1], r[2], r[3]);
        *(float4*)&op[4] = make_float4(r[4], r[5], r[6], r[7]);
    }
}

// ---------------- launch ----------------------------------------------------
extern "C" void kernel_launch(void* const* d_in, const int* in_sizes, int n_in,
                              void* d_out, int out_size) {
    const float* x         = (const float*)d_in[0];
    const float* t_emb     = (const float*)d_in[1];
    const float* c_emb     = (const float*)d_in[2];
    const float* proj_dw   = (const float*)d_in[3];
    const float* proj_dw_b = (const float*)d_in[4];
    const float* proj_pw   = (const float*)d_in[5];
    const float* proj_pw_b = (const float*)d_in[6];
    const float* r_w1      = (const float*)d_in[7];
    const float* r_b1      = (const float*)d_in[8];
    const float* r_w2      = (const float*)d_in[9];
    const float* r_b2      = (const float*)d_in[10];
    const float* exp_dw    = (const float*)d_in[11];
    const float* exp_dw_b  = (const float*)d_in[12];
    const float* exp_pw    = (const float*)d_in[13];
    const float* exp_pw_b  = (const float*)d_in[14];

    float* out        = (float*)d_out;
    float* out_logits = out + (size_t)Bn * C * P;

    dw_proj_kernel<<<(Bn*C*1024 + 255) / 256, 256>>>(x, proj_dw, proj_dw_b);
    pw_proj_kernel<<<dim3(P / 64, Bn), 256>>>(proj_pw, proj_pw_b);
    pool_kernel<<<Bn * C, 256>>>();
    router_kernel<<<Bn, 512>>>(t_emb, c_emb, r_w1, r_b1, r_w2, r_b2, out_logits);
    dw_exp_kernel<<<(Bn*NK*C*1024 + 255) / 256, 256>>>(exp_dw, exp_dw_b);
    pw_exp_kernel<<<dim3(P / 64, Bn), 256>>>(exp_pw, exp_pw_b, out);
}

// round 4
// speedup vs baseline: 3.4793x; 2.3442x over previous
#include <cuda_runtime.h>
#include <math.h>

#define Bn 16
#define C  128
#define P  4096      // 64*64
#define TD 256
#define CD 256
#define E  8
#define NK 2

// ---------------- scratch (static device arrays) ---------------------------
__device__ float g_t1[Bn*C*P];          // dwconv(proj) output
__device__ float g_xproj[Bn*C*P];       // x_proj
__device__ float g_t2[Bn*NK*C*P];       // expert dwconv outputs (routed)
__device__ float g_pooled[Bn*C];
__device__ int   g_eidx[Bn*NK];
__device__ float g_ew[Bn*NK];

__device__ __forceinline__ float silu_f(float v) {
    return v / (1.f + __expf(-v));
}

// tf32 round (rna) of an fp32 value, kept in a b32 reg
__device__ __forceinline__ float tf32r(float x) {
    unsigned u;
    asm("cvt.rna.tf32.f32 %0, %1;" : "=r"(u) : "f"(x));
    return __uint_as_float(u);
}

// D += A(16x8,row) * B(8x8,col), tf32 inputs / f32 accum
__device__ __forceinline__ void mma_tf32(float* c,
                                         unsigned a0, unsigned a1, unsigned a2, unsigned a3,
                                         unsigned b0, unsigned b1) {
    asm volatile("mma.sync.aligned.m16n8k8.row.col.f32.tf32.tf32.f32 "
                 "{%0,%1,%2,%3}, {%4,%5,%6,%7}, {%8,%9}, {%0,%1,%2,%3};"
                 : "+f"(c[0]), "+f"(c[1]), "+f"(c[2]), "+f"(c[3])
                 : "r"(a0), "r"(a1), "r"(a2), "r"(a3), "r"(b0), "r"(b1));
}

// ---------------- 1) proj depthwise 3x3 (4 px / thread) --------------------
__global__ void dw_proj_kernel(const float* __restrict__ x,
                               const float* __restrict__ w,
                               const float* __restrict__ bias) {
    int idx = blockIdx.x * blockDim.x + threadIdx.x;   // over Bn*C*1024
    if (idx >= Bn*C*1024) return;
    int q = idx & 1023;
    int px0 = (q & 15) << 2;
    int py  = q >> 4;
    int plane = idx >> 10;            // b*C + c
    int c = plane & 127;
    const float* xp = x + ((size_t)plane << 12);
    const float* wc = w + c * 9;
    float bb = bias[c];
    float acc0 = bb, acc1 = bb, acc2 = bb, acc3 = bb;
    #pragma unroll
    for (int dy = -1; dy <= 1; dy++) {
        int yy = py + dy;
        if ((unsigned)yy >= 64u) continue;
        const float* row = xp + (yy << 6);
        float4 m = *(const float4*)&row[px0];
        float rl = (px0 == 0)  ? 0.f : row[px0 - 1];
        float rr = (px0 == 60) ? 0.f : row[px0 + 4];
        float w0 = wc[(dy+1)*3], w1 = wc[(dy+1)*3+1], w2 = wc[(dy+1)*3+2];
        acc0 += w0*rl  + w1*m.x + w2*m.y;
        acc1 += w0*m.x + w1*m.y + w2*m.z;
        acc2 += w0*m.y + w1*m.z + w2*m.w;
        acc3 += w0*m.z + w1*m.w + w2*rr;
    }
    *(float4*)&g_t1[((size_t)plane << 12) + (py << 6) + px0] =
        make_float4(acc0, acc1, acc2, acc3);
}

// ---------------- 2) proj pointwise 1x1: tf32 tensor-core GEMM -------------
// block 256 thr (8 warps). Block tile 128co x 64px, warp tile 32x32, KC=32.
#define WS_P 36     // Wsm row stride (32 + 4 pad): conflict-free A-frag LDS
#define BS_S 68     // Bsm row stride (64 + 4 pad)
__global__ __launch_bounds__(256)
void pw_proj_kernel(const float* __restrict__ Wm, const float* __restrict__ bias) {
    int b  = blockIdx.y;
    int p0 = blockIdx.x * 64;
    int tx = threadIdx.x;
    int wid = tx >> 5, lane = tx & 31;
    int wm = wid >> 1, wn = wid & 1;       // 4 x 2 warp grid
    int g = lane >> 2, t4 = lane & 3;
    __shared__ float Wsm[128 * WS_P];      // [co][k]
    __shared__ float Bsm[32 * BS_S];       // [k][px]
    float acc[2][4][4];
    #pragma unroll
    for (int i = 0; i < 2; i++)
        #pragma unroll
        for (int j = 0; j < 4; j++)
            #pragma unroll
            for (int l = 0; l < 4; l++) acc[i][j][l] = 0.f;

    const float* tin = g_t1 + (((size_t)b * C) << 12) + p0;
    for (int c0 = 0; c0 < C; c0 += 32) {
        __syncthreads();
        #pragma unroll
        for (int i = 0; i < 4; i++) {           // W chunk: 128x32 fl = 1024 f4
            int slot = i * 256 + tx;
            int co = slot >> 3, k4 = slot & 7;
            float4 v = *(const float4*)&Wm[co * C + c0 + k4 * 4];
            float* d = &Wsm[co * WS_P + k4 * 4];
            d[0] = tf32r(v.x); d[1] = tf32r(v.y); d[2] = tf32r(v.z); d[3] = tf32r(v.w);
        }
        #pragma unroll
        for (int i = 0; i < 2; i++) {           // B chunk: 32x64 fl = 512 f4
            int slot = i * 256 + tx;
            int k = slot >> 4, px4 = slot & 15;
            float4 v = *(const float4*)&tin[(size_t)(c0 + k) * P + px4 * 4];
            float* d = &Bsm[k * BS_S + px4 * 4];
            d[0] = tf32r(v.x); d[1] = tf32r(v.y); d[2] = tf32r(v.z); d[3] = tf32r(v.w);
        }
        __syncthreads();
        #pragma unroll
        for (int kk = 0; kk < 4; kk++) {
            int kb = kk * 8;
            unsigned af[2][4];
            #pragma unroll
            for (int mt = 0; mt < 2; mt++) {
                int r0 = wm * 32 + mt * 16 + g;
                af[mt][0] = __float_as_uint(Wsm[r0 * WS_P + kb + t4]);
                af[mt][1] = __float_as_uint(Wsm[(r0 + 8) * WS_P + kb + t4]);
                af[mt][2] = __float_as_uint(Wsm[r0 * WS_P + kb + t4 + 4]);
                af[mt][3] = __float_as_uint(Wsm[(r0 + 8) * WS_P + kb + t4 + 4]);
            }
            #pragma unroll
            for (int nt = 0; nt < 4; nt++) {
                int col = wn * 32 + nt * 8 + g;
                unsigned b0 = __float_as_uint(Bsm[(kb + t4) * BS_S + col]);
                unsigned b1 = __float_as_uint(Bsm[(kb + t4 + 4) * BS_S + col]);
                #pragma unroll
                for (int mt = 0; mt < 2; mt++)
                    mma_tf32(acc[mt][nt], af[mt][0], af[mt][1], af[mt][2], af[mt][3], b0, b1);
            }
        }
    }
    #pragma unroll
    for (int mt = 0; mt < 2; mt++) {
        int r0 = wm * 32 + mt * 16 + g;
        float bb0 = bias[r0], bb8 = bias[r0 + 8];
        #pragma unroll
        for (int nt = 0; nt < 4; nt++) {
            int col = p0 + wn * 32 + nt * 8 + 2 * t4;
            float* o0 = g_xproj + ((((size_t)b * C) + r0) << 12) + col;
            float* o8 = g_xproj + ((((size_t)b * C) + r0 + 8) << 12) + col;
            *(float2*)o0 = make_float2(acc[mt][nt][0] + bb0, acc[mt][nt][1] + bb0);
            *(float2*)o8 = make_float2(acc[mt][nt][2] + bb8, acc[mt][nt][3] + bb8);
        }
    }
}

// ---------------- 3) global average pool -----------------------------------
__global__ void pool_kernel() {
    int plane = blockIdx.x;           // b*C + c
    const float4* p = (const float4*)(g_xproj + ((size_t)plane << 12));
    float s = 0.f;
    for (int i = threadIdx.x; i < 1024; i += 256) {
        float4 v = p[i];
        s += v.x + v.y + v.z + v.w;
    }
    __shared__ float sm[8];
    #pragma unroll
    for (int o = 16; o; o >>= 1) s += __shfl_down_sync(0xffffffffu, s, o);
    if ((threadIdx.x & 31) == 0) sm[threadIdx.x >> 5] = s;
    __syncthreads();
    if (threadIdx.x == 0) {
        float t = 0.f;
        #pragma unroll
        for (int i = 0; i < 8; i++) t += sm[i];
        g_pooled[plane] = t * (1.f / 4096.f);
    }
}

// ---------------- 4) router: per-b block, fused MLP+top2 -------------------
__global__ __launch_bounds__(1024)
void router_kernel(const float* __restrict__ t_emb,
                   const float* __restrict__ c_emb,
                   const float* __restrict__ W1, const float* __restrict__ b1,
                   const float* __restrict__ W2, const float* __restrict__ b2,
                   float* __restrict__ out_logits) {
    int b = blockIdx.x;
    __shared__ float feat[C + TD + CD];
    __shared__ float hpart[8][C];
    __shared__ float h[C];
    __shared__ float lgp[8][E];
    __shared__ float lg[E];
    int t = threadIdx.x;
    if (t < C + TD + CD) {
        float v;
        if (t < C)            v = g_pooled[b * C + t];
        else if (t < C + TD)  v = t_emb[b * TD + (t - C)];
        else                  v = c_emb[b * CD + (t - C - TD)];
        feat[t] = v;
    }
    __syncthreads();
    int co = t & 127, chunk = t >> 7;           // 8 chunks of 80 features
    {
        float acc = 0.f;
        int f0 = chunk * 80;
        #pragma unroll 8
        for (int f = f0; f < f0 + 80; f++) acc += feat[f] * W1[f * C + co];
        hpart[chunk][co] = acc;
    }
    __syncthreads();
    if (t < C) {
        float v = b1[t];
        #pragma unroll
        for (int i = 0; i < 8; i++) v += hpart[i][t];
        h[t] = silu_f(v);
    }
    __syncthreads();
    if (t < 64) {
        int e = t & 7, pp = t >> 3;
        float a = 0.f;
        int c0 = pp * 16;
        #pragma unroll
        for (int ci = c0; ci < c0 + 16; ci++) a += h[ci] * W2[ci * E + e];
        lgp[pp][e] = a;
    }
    __syncthreads();
    if (t < E) {
        float a = b2[t];
        #pragma unroll
        for (int i = 0; i < 8; i++) a += lgp[i][t];
        lg[t] = a;
        out_logits[b * E + t] = a;
    }
    __syncthreads();
    if (t == 0) {
        int i0 = 0; float v0 = lg[0];
        for (int e = 1; e < E; e++) if (lg[e] > v0) { v0 = lg[e]; i0 = e; }
        int i1 = -1; float v1 = -3.0e38f;
        for (int e = 0; e < E; e++) {
            if (e == i0) continue;
            if (lg[e] > v1) { v1 = lg[e]; i1 = e; }
        }
        float w0 = 1.f / (1.f + __expf(v1 - v0));
        g_eidx[b*2]   = i0;  g_eidx[b*2+1] = i1;
        g_ew[b*2]     = w0;  g_ew[b*2+1]   = 1.f - w0;
    }
}

// ---------------- 5) routed expert depthwise 3x3 (4 px / thread) -----------
__global__ void dw_exp_kernel(const float* __restrict__ w,
                              const float* __restrict__ bias) {
    int idx = blockIdx.x * blockDim.x + threadIdx.x;   // over Bn*NK*C*1024
    if (idx >= Bn*NK*C*1024) return;
    int q = idx & 1023;
    int px0 = (q & 15) << 2;
    int py  = q >> 4;
    int rest = idx >> 10;
    int c = rest & 127;
    int k = (rest >> 7) & 1;
    int b = rest >> 8;
    int e = g_eidx[b * NK + k];
    const float* xp = g_xproj + ((((size_t)b * C) + c) << 12);
    const float* wc = w + ((size_t)e * C + c) * 9;
    float bb = bias[e * C + c];
    float acc0 = bb, acc1 = bb, acc2 = bb, acc3 = bb;
    #pragma unroll
    for (int dy = -1; dy <= 1; dy++) {
        int yy = py + dy;
        if ((unsigned)yy >= 64u) continue;
        const float* row = xp + (yy << 6);
        float4 m = *(const float4*)&row[px0];
        float rl = (px0 == 0)  ? 0.f : row[px0 - 1];
        float rr = (px0 == 60) ? 0.f : row[px0 + 4];
        float w0 = wc[(dy+1)*3], w1 = wc[(dy+1)*3+1], w2 = wc[(dy+1)*3+2];
        acc0 += w0*rl  + w1*m.x + w2*m.y;
        acc1 += w0*m.x + w1*m.y + w2*m.z;
        acc2 += w0*m.y + w1*m.z + w2*m.w;
        acc3 += w0*m.z + w1*m.w + w2*rr;
    }
    *(float4*)&g_t2[((size_t)(((b*2 + k) * C) + c) << 12) + (py << 6) + px0] =
        make_float4(acc0, acc1, acc2, acc3);
}

// ---------------- 6) expert pw GEMM x2 (tf32 MMA) + silu + mix -------------
#define WS_E 20     // Wsm row stride for KC=16 (16 + 4 pad)
__global__ __launch_bounds__(256)
void pw_exp_kernel(const float* __restrict__ Wm, const float* __restrict__ bias,
                   float* __restrict__ out) {
    int b  = blockIdx.y;
    int p0 = blockIdx.x * 64;
    int tx = threadIdx.x;
    int wid = tx >> 5, lane = tx & 31;
    int wm = wid >> 1, wn = wid & 1;
    int g = lane >> 2, t4 = lane & 3;
    int e0 = g_eidx[b*2], e1 = g_eidx[b*2+1];
    float rw0 = g_ew[b*2], rw1 = g_ew[b*2+1];
    __shared__ float Wsm0[128 * WS_E], Wsm1[128 * WS_E];
    __shared__ float Bsm0[16 * BS_S],  Bsm1[16 * BS_S];
    float a0c[2][4][4], a1c[2][4][4];
    #pragma unroll
    for (int i = 0; i < 2; i++)
        #pragma unroll
        for (int j = 0; j < 4; j++)
            #pragma unroll
            for (int l = 0; l < 4; l++) { a0c[i][j][l] = 0.f; a1c[i][j][l] = 0.f; }

    const float* t0 = g_t2 + (((size_t)(b*2 + 0) * C) << 12) + p0;
    const float* t1 = g_t2 + (((size_t)(b*2 + 1) * C) << 12) + p0;
    const float* W0 = Wm + (size_t)e0 * C * C;
    const float* W1 = Wm + (size_t)e1 * C * C;
    for (int c0 = 0; c0 < C; c0 += 16) {
        __syncthreads();
        #pragma unroll
        for (int i = 0; i < 2; i++) {           // W chunks: 128x16 fl = 512 f4 each
            int slot = i * 256 + tx;
            int co = slot >> 2, k4 = slot & 3;
            float4 v0 = *(const float4*)&W0[co * C + c0 + k4 * 4];
            float4 v1 = *(const float4*)&W1[co * C + c0 + k4 * 4];
            float* d0 = &Wsm0[co * WS_E + k4 * 4];
            float* d1 = &Wsm1[co * WS_E + k4 * 4];
            d0[0]=tf32r(v0.x); d0[1]=tf32r(v0.y); d0[2]=tf32r(v0.z); d0[3]=tf32r(v0.w);
            d1[0]=tf32r(v1.x); d1[1]=tf32r(v1.y); d1[2]=tf32r(v1.z); d1[3]=tf32r(v1.w);
        }
        {                                        // B chunks: 16x64 fl = 256 f4 each
            int k = tx >> 4, px4 = tx & 15;
            float4 v0 = *(const float4*)&t0[(size_t)(c0 + k) * P + px4 * 4];
            float4 v1 = *(const float4*)&t1[(size_t)(c0 + k) * P + px4 * 4];
            float* d0 = &Bsm0[k * BS_S + px4 * 4];
            float* d1 = &Bsm1[k * BS_S + px4 * 4];
            d0[0]=tf32r(v0.x); d0[1]=tf32r(v0.y); d0[2]=tf32r(v0.z); d0[3]=tf32r(v0.w);
            d1[0]=tf32r(v1.x); d1[1]=tf32r(v1.y); d1[2]=tf32r(v1.z); d1[3]=tf32r(v1.w);
        }
        __syncthreads();
        #pragma unroll
        for (int kk = 0; kk < 2; kk++) {
            int kb = kk * 8;
            unsigned af0[2][4], af1[2][4];
            #pragma unroll
            for (int mt = 0; mt < 2; mt++) {
                int r0 = wm * 32 + mt * 16 + g;
                af0[mt][0] = __float_as_uint(Wsm0[r0 * WS_E + kb + t4]);
                af0[mt][1] = __float_as_uint(Wsm0[(r0 + 8) * WS_E + kb + t4]);
                af0[mt][2] = __float_as_uint(Wsm0[r0 * WS_E + kb + t4 + 4]);
                af0[mt][3] = __float_as_uint(Wsm0[(r0 + 8) * WS_E + kb + t4 + 4]);
                af1[mt][0] = __float_as_uint(Wsm1[r0 * WS_E + kb + t4]);
                af1[mt][1] = __float_as_uint(Wsm1[(r0 + 8) * WS_E + kb + t4]);
                af1[mt][2] = __float_as_uint(Wsm1[r0 * WS_E + kb + t4 + 4]);
                af1[mt][3] = __float_as_uint(Wsm1[(r0 + 8) * WS_E + kb + t4 + 4]);
            }
            #pragma unroll
            for (int nt = 0; nt < 4; nt++) {
                int col = wn * 32 + nt * 8 + g;
                unsigned b00 = __float_as_uint(Bsm0[(kb + t4) * BS_S + col]);
                unsigned b01 = __float_as_uint(Bsm0[(kb + t4 + 4) * BS_S + col]);
                unsigned b10 = __float_as_uint(Bsm1[(kb + t4) * BS_S + col]);
                unsigned b11 = __float_as_uint(Bsm1[(kb + t4 + 4) * BS_S + col]);
                #pragma unroll
                for (int mt = 0; mt < 2; mt++) {
                    mma_tf32(a0c[mt][nt], af0[mt][0], af0[mt][1], af0[mt][2], af0[mt][3], b00, b01);
                    mma_tf32(a1c[mt][nt], af1[mt][0], af1[mt][1], af1[mt][2], af1[mt][3], b10, b11);
                }
            }
        }
    }
    #pragma unroll
    for (int mt = 0; mt < 2; mt++) {
        int r0 = wm * 32 + mt * 16 + g;
        float b00 = bias[e0 * C + r0], b08 = bias[e0 * C + r0 + 8];
        float b10 = bias[e1 * C + r0], b18 = bias[e1 * C + r0 + 8];
        #pragma unroll
        for (int nt = 0; nt < 4; nt++) {
            int col = p0 + wn * 32 + nt * 8 + 2 * t4;
            float* o0 = out + ((((size_t)b * C) + r0) << 12) + col;
            float* o8 = out + ((((size_t)b * C) + r0 + 8) << 12) + col;
            float v0 = rw0 * silu_f(a0c[mt][nt][0] + b00) + rw1 * silu_f(a1c[mt][nt][0] + b10);
            float v1 = rw0 * silu_f(a0c[mt][nt][1] + b00) + rw1 * silu_f(a1c[mt][nt][1] + b10);
            float v2 = rw0 * silu_f(a0c[mt][nt][2] + b08) + rw1 * silu_f(a1c[mt][nt][2] + b18);
            float v3 = rw0 * silu_f(a0c[mt][nt][3] + b08) + rw1 * silu_f(a1c[mt][nt][3] + b18);
            *(float2*)o0 = make_float2(v0, v1);
            *(float2*)o8 = make_float2(v2, v3);
        }
    }
}

// ---------------- launch ----------------------------------------------------
extern "C" void kernel_launch(void* const* d_in, const int* in_sizes, int n_in,
                              void* d_out, int out_size) {
    const float* x         = (const float*)d_in[0];
    const float* t_emb     = (const float*)d_in[1];
    const float* c_emb     = (const float*)d_in[2];
    const float* proj_dw   = (const float*)d_in[3];
    const float* proj_dw_b = (const float*)d_in[4];
    const float* proj_pw   = (const float*)d_in[5];
    const float* proj_pw_b = (const float*)d_in[6];
    const float* r_w1      = (const float*)d_in[7];
    const float* r_b1      = (const float*)d_in[8];
    const float* r_w2      = (const float*)d_in[9];
    const float* r_b2      = (const float*)d_in[10];
    const float* exp_dw    = (const float*)d_in[11];
    const float* exp_dw_b  = (const float*)d_in[12];
    const float* exp_pw    = (const float*)d_in[13];
    const float* exp_pw_b  = (const float*)d_in[14];

    float* out        = (float*)d_out;
    float* out_logits = out + (size_t)Bn * C * P;

    dw_proj_kernel<<<(Bn*C*1024 + 255) / 256, 256>>>(x, proj_dw, proj_dw_b);
    pw_proj_kernel<<<dim3(P / 64, Bn), 256>>>(proj_pw, proj_pw_b);
    pool_kernel<<<Bn * C, 256>>>();
    router_kernel<<<Bn, 1024>>>(t_emb, c_emb, r_w1, r_b1, r_w2, r_b2, out_logits);
    dw_exp_kernel<<<(Bn*NK*C*1024 + 255) / 256, 256>>>(exp_dw, exp_dw_b);
    pw_exp_kernel<<<dim3(P / 64, Bn), 256>>>(exp_pw, exp_pw_b, out);
}